// round 1
// baseline (speedup 1.0000x reference)
#include <cuda_runtime.h>
#include <math.h>

// BFP quant-dequant: x[8192, 12284] fp32, block=8 along last dim.
// step = 2^(frexp_exp(maxabs) - 7); q = clip(rint(x/step), -128, 127); out = q*step.
// Last block per row has only 4 real elements (12284 = 8*1535 + 4).

#define ROWS 8192
#define COLS 12284
#define BLOCKS_PER_ROW 1536   // ceil(12284/8)
#define FULL_BLOCKS 1535

__global__ void bfp_kernel(const float* __restrict__ x, float* __restrict__ out) {
    const int row = blockIdx.y;
    const int blk = blockIdx.x * blockDim.x + threadIdx.x;   // 0..1535 exactly (6*256)
    const size_t base = (size_t)row * COLS + (size_t)blk * 8;
    const bool full = (blk < FULL_BLOCKS);

    float4 a = *reinterpret_cast<const float4*>(x + base);
    float4 b = make_float4(0.f, 0.f, 0.f, 0.f);
    if (full) b = *reinterpret_cast<const float4*>(x + base + 4);

    float m = fmaxf(fmaxf(fabsf(a.x), fabsf(a.y)), fmaxf(fabsf(a.z), fabsf(a.w)));
    m = fmaxf(m, fmaxf(fmaxf(fabsf(b.x), fabsf(b.y)), fmaxf(fabsf(b.z), fabsf(b.w))));

    int e;
    frexpf(m, &e);                       // m == 0 -> e = 0, matching jnp.frexp
    const float step     = ldexpf(1.0f, e - 7);   // exact power of two
    const float inv_step = ldexpf(1.0f, 7 - e);   // exact power of two

    #define QDQ(v) (fminf(fmaxf(rintf((v) * inv_step), -128.0f), 127.0f) * step)
    float4 oa, ob;
    oa.x = QDQ(a.x); oa.y = QDQ(a.y); oa.z = QDQ(a.z); oa.w = QDQ(a.w);
    ob.x = QDQ(b.x); ob.y = QDQ(b.y); ob.z = QDQ(b.z); ob.w = QDQ(b.w);
    #undef QDQ

    *reinterpret_cast<float4*>(out + base) = oa;
    if (full) *reinterpret_cast<float4*>(out + base + 4) = ob;
}

extern "C" void kernel_launch(void* const* d_in, const int* in_sizes, int n_in,
                              void* d_out, int out_size) {
    const float* x = (const float*)d_in[0];
    float* out = (float*)d_out;
    dim3 grid(BLOCKS_PER_ROW / 256, ROWS);   // (6, 8192)
    bfp_kernel<<<grid, 256>>>(x, out);
}